// round 15
// baseline (speedup 1.0000x reference)
#include <cuda_runtime.h>
#include <cooperative_groups.h>

namespace cg = cooperative_groups;

#define B 64
#define N 16384
#define M 64
#define FULLM 0xFFFFFFFFu

// scratch (device globals — no allocation allowed)
__device__ float g_s[B * N];        // exp(beta*cos) from k1
__device__ float g_part[B * 256];   // per-block partial sums (k1 grid.x = 256)

// ---------------------------------------------------------------------------
// k1 (proven ~41.7us): exp(beta*cos) per row + deterministic per-block
// partial sum. 8 lanes/row, 2 rows/thread -> 4 LDG.128.CS in flight; ~55 regs.
// Block = 256 thr -> 64 rows. Grid = (256, B).
// ---------------------------------------------------------------------------
__global__ __launch_bounds__(256) void k1_logits(
    const float* __restrict__ key,    // [B, M]
    const float* __restrict__ beta,   // [B, 1]
    const float* __restrict__ mem)    // [B, N, M]
{
    const int b    = blockIdx.y;
    const int tid  = threadIdx.x;
    const int l    = tid & 7;
    const int grp  = tid >> 3;
    const int row0 = blockIdx.x * 64;

    const float4* kp = reinterpret_cast<const float4*>(key + b * M);
    const float4 ka = kp[l];
    const float4 kb = kp[l + 8];
    float ks = ka.x * ka.x + ka.y * ka.y + ka.z * ka.z + ka.w * ka.w
             + kb.x * kb.x + kb.y * kb.y + kb.z * kb.z + kb.w * kb.w;

    float4 ma[2], mb[2];
#pragma unroll
    for (int u = 0; u < 2; ++u) {
        const int row = row0 + u * 32 + grp;
        const float4* mp = reinterpret_cast<const float4*>(
            mem + ((size_t)b * N + row) * M);
        ma[u] = __ldcs(mp + l);
        mb[u] = __ldcs(mp + l + 8);
    }

    float dt[2], ms[2];
#pragma unroll
    for (int u = 0; u < 2; ++u) {
        dt[u] = ka.x * ma[u].x + ka.y * ma[u].y + ka.z * ma[u].z + ka.w * ma[u].w
              + kb.x * mb[u].x + kb.y * mb[u].y + kb.z * mb[u].z + kb.w * mb[u].w;
        ms[u] = ma[u].x * ma[u].x + ma[u].y * ma[u].y + ma[u].z * ma[u].z + ma[u].w * ma[u].w
              + mb[u].x * mb[u].x + mb[u].y * mb[u].y + mb[u].z * mb[u].z + mb[u].w * mb[u].w;
    }

#pragma unroll
    for (int off = 1; off <= 4; off <<= 1) {
        ks    += __shfl_xor_sync(FULLM, ks,    off);
        dt[0] += __shfl_xor_sync(FULLM, dt[0], off);
        dt[1] += __shfl_xor_sync(FULLM, dt[1], off);
        ms[0] += __shfl_xor_sync(FULLM, ms[0], off);
        ms[1] += __shfl_xor_sync(FULLM, ms[1], off);
    }

    float esum = 0.0f;
    if (l == 0) {
        const float kn = sqrtf(ks);
        const float be = __ldg(beta + b);
#pragma unroll
        for (int u = 0; u < 2; ++u) {
            const int row = row0 + u * 32 + grp;
            const float denom = fmaxf(kn * sqrtf(ms[u]), 1e-8f);
            const float e = __expf(be * (dt[u] / denom));
            g_s[b * N + row] = e;
            esum += e;
        }
    }

    __shared__ float sred[8];
#pragma unroll
    for (int o = 16; o > 0; o >>= 1)
        esum += __shfl_xor_sync(FULLM, esum, o);
    if ((tid & 31) == 0) sred[tid >> 5] = esum;
    __syncthreads();
    if (tid == 0) {
        float s = 0.0f;
#pragma unroll
        for (int w = 0; w < 8; ++w) s += sred[w];
        g_part[b * 256 + blockIdx.x] = s;
    }
}

// ---------------------------------------------------------------------------
// k2 with PDL, linear split: ws = gS*conv(e) + og*conv(l).
// Preamble (overlaps k1 drain): load last, compute cl = og*conv(l) fully.
// Post-sync: 4 vector g_s loads, per-warp redundant S-reduce (no barrier),
// publish raw e edges, ONE barrier, conv(e)+combine+pow, reduce, cluster
// combine (fixed rank order), store. Cluster-4, 256 CTAs x 256 thr.
// ---------------------------------------------------------------------------
__global__ __launch_bounds__(256) __cluster_dims__(4, 1, 1)
void k2_address(
    const float* __restrict__ gate,     // [B,1]
    const float* __restrict__ shift,    // [B,3]
    const float* __restrict__ sharpen,  // [B,1]
    const float* __restrict__ last,     // [B,N]
    float* __restrict__ out)            // [B,N]
{
    cg::cluster_group cluster = cg::this_cluster();

    const int cta  = blockIdx.x;     // 0..255
    const int b    = cta >> 2;
    const int q    = cta & 3;        // quarter of the batch (== cluster rank)
    const int tid  = threadIdx.x;
    const int warp = tid >> 5;       // 0..7
    const int lane = tid & 31;

    __shared__ float sred[8];
    __shared__ float eL[32], eR[32];         // edge tables (reused l then e)
    __shared__ float sCL, sCR;               // CTA-circular edges (l then e)
    __shared__ float cpsum;                  // DSMEM target

    // ======= PDL preamble: full last-side convolution =======
    const int base4 = (b << 12) + (q << 10);
    const float4* lp4 = reinterpret_cast<const float4*>(last);

    float4 a4[4];
#pragma unroll
    for (int k = 0; k < 4; ++k)
        a4[k] = lp4[base4 + k * 256 + tid];

    // CTA-circular edge element indices (within batch b)
    int edgeIdx = -1;
    if (tid == 0)   edgeIdx = b * N + (((q << 12) + N - 1) & (N - 1));
    if (tid == 255) edgeIdx = b * N + (((q << 12) + 4096) & (N - 1));

    const float g  = __ldg(gate + b);
    const float og = 1.0f - g;
    const float s0 = __ldg(shift + b * 3 + 0);
    const float s1 = __ldg(shift + b * 3 + 1);
    const float s2 = __ldg(shift + b * 3 + 2);
    const float sh = __ldg(sharpen + b);
    const float s0l = og * s0, s1l = og * s1, s2l = og * s2;

    // publish l edges
    if (lane == 0) {
#pragma unroll
        for (int k = 0; k < 4; ++k) eL[warp * 4 + k] = a4[k].x;
    }
    if (lane == 31) {
#pragma unroll
        for (int k = 0; k < 4; ++k) eR[warp * 4 + k] = a4[k].w;
    }
    if (tid == 0)   sCL = last[edgeIdx];
    if (tid == 255) sCR = last[edgeIdx];
    __syncthreads();

    // cl = og * conv(l), kept in registers
    float4 cl[4];
#pragma unroll
    for (int k = 0; k < 4; ++k) {
        float left = __shfl_up_sync(FULLM, a4[k].w, 1);
        if (lane == 0)
            left = (warp > 0) ? eR[(warp - 1) * 4 + k]
                 : (k > 0)    ? eR[7 * 4 + (k - 1)]
                              : sCL;
        float right = __shfl_down_sync(FULLM, a4[k].x, 1);
        if (lane == 31)
            right = (warp < 7) ? eL[(warp + 1) * 4 + k]
                  : (k < 3)    ? eL[k + 1]
                               : sCR;
        cl[k].x = s0l * left    + s1l * a4[k].x + s2l * a4[k].y;
        cl[k].y = s0l * a4[k].x + s1l * a4[k].y + s2l * a4[k].z;
        cl[k].z = s0l * a4[k].y + s1l * a4[k].z + s2l * a4[k].w;
        cl[k].w = s0l * a4[k].z + s1l * a4[k].w + s2l * right;
    }
    __syncthreads();  // edge tables free for reuse

    // ======= wait for k1 grid completion (memory-visible) =======
    cudaGridDependencySynchronize();

    // post-sync loads (front-batched)
    const float4* sp4 = reinterpret_cast<const float4*>(g_s);
    float4 e4[4];
#pragma unroll
    for (int k = 0; k < 4; ++k)
        e4[k] = sp4[base4 + k * 256 + tid];

    float edgeS = 0.0f;
    if (edgeIdx >= 0) edgeS = g_s[edgeIdx];

    // publish raw e edges (no gS dependency) — overlap with S reduce below
    if (lane == 0) {
#pragma unroll
        for (int k = 0; k < 4; ++k) eL[warp * 4 + k] = e4[k].x;
    }
    if (lane == 31) {
#pragma unroll
        for (int k = 0; k < 4; ++k) eR[warp * 4 + k] = e4[k].w;
    }
    if (tid == 0)   sCL = edgeS;
    if (tid == 255) sCR = edgeS;

    // per-warp redundant softmax denominator (bitwise identical across warps)
    const float* pp = g_part + b * 256;
    float S = 0.0f;
#pragma unroll
    for (int j = 0; j < 8; ++j) S += pp[j * 32 + lane];
#pragma unroll
    for (int o = 16; o > 0; o >>= 1)
        S += __shfl_xor_sync(FULLM, S, o);
    const float gS = g / S;
    const float s0g = gS * s0, s1g = gS * s1, s2g = gS * s2;

    __syncthreads();  // e edge tables ready

    // ws = gS*conv(e) + cl ; p = ws^sh
    float4 p4[4];
    float psum = 0.0f;
#pragma unroll
    for (int k = 0; k < 4; ++k) {
        float left = __shfl_up_sync(FULLM, e4[k].w, 1);
        if (lane == 0)
            left = (warp > 0) ? eR[(warp - 1) * 4 + k]
                 : (k > 0)    ? eR[7 * 4 + (k - 1)]
                              : sCL;
        float right = __shfl_down_sync(FULLM, e4[k].x, 1);
        if (lane == 31)
            right = (warp < 7) ? eL[(warp + 1) * 4 + k]
                  : (k < 3)    ? eL[k + 1]
                               : sCR;

        float4 ws;
        ws.x = fmaf(s0g, left,    fmaf(s1g, e4[k].x, fmaf(s2g, e4[k].y, cl[k].x)));
        ws.y = fmaf(s0g, e4[k].x, fmaf(s1g, e4[k].y, fmaf(s2g, e4[k].z, cl[k].y)));
        ws.z = fmaf(s0g, e4[k].y, fmaf(s1g, e4[k].z, fmaf(s2g, e4[k].w, cl[k].z)));
        ws.w = fmaf(s0g, e4[k].z, fmaf(s1g, e4[k].w, fmaf(s2g, right,   cl[k].w)));

        p4[k].x = __powf(ws.x, sh);
        p4[k].y = __powf(ws.y, sh);
        p4[k].z = __powf(ws.z, sh);
        p4[k].w = __powf(ws.w, sh);
        psum += p4[k].x + p4[k].y + p4[k].z + p4[k].w;
    }

    // ---- CTA psum reduce (deterministic) ----
#pragma unroll
    for (int o = 16; o > 0; o >>= 1)
        psum += __shfl_xor_sync(FULLM, psum, o);
    if (lane == 0) sred[warp] = psum;
    __syncthreads();
    if (tid == 0) {
        float x = 0.0f;
#pragma unroll
        for (int w = 0; w < 8; ++w) x += sred[w];
        cpsum = x;
    }

    // ---- cluster combine via DSMEM (fixed rank order -> deterministic) ----
    cluster.sync();
    float P = 0.0f;
#pragma unroll
    for (int r = 0; r < 4; ++r)
        P += *cluster.map_shared_rank(&cpsum, r);
    cluster.sync();  // keep peer smem alive until everyone has read

    const float invP = 1.0f / (P + 1e-16f);

    float4* op4 = reinterpret_cast<float4*>(out);
#pragma unroll
    for (int k = 0; k < 4; ++k) {
        float4 p = p4[k];
        p.x *= invP; p.y *= invP; p.z *= invP; p.w *= invP;
        op4[base4 + k * 256 + tid] = p;
    }
}

extern "C" void kernel_launch(void* const* d_in, const int* in_sizes, int n_in,
                              void* d_out, int out_size) {
    const float* key     = (const float*)d_in[0];
    const float* beta    = (const float*)d_in[1];
    const float* gate    = (const float*)d_in[2];
    const float* shift   = (const float*)d_in[3];
    const float* sharpen = (const float*)d_in[4];
    const float* last    = (const float*)d_in[5];
    const float* mem     = (const float*)d_in[6];
    float* out = (float*)d_out;

    dim3 g1(N / 64, B);
    k1_logits<<<g1, 256>>>(key, beta, mem);

    cudaLaunchConfig_t cfg = {};
    cfg.gridDim  = dim3(B * 4);
    cfg.blockDim = dim3(256);
    cudaLaunchAttribute attrs[1];
    attrs[0].id = cudaLaunchAttributeProgrammaticStreamSerialization;
    attrs[0].val.programmaticStreamSerializationAllowed = 1;
    cfg.attrs = attrs;
    cfg.numAttrs = 1;
    cudaLaunchKernelEx(&cfg, k2_address, gate, shift, sharpen, last, out);
}

// round 16
// speedup vs baseline: 1.3224x; 1.3224x over previous
#include <cuda_runtime.h>
#include <cooperative_groups.h>

namespace cg = cooperative_groups;

#define B 64
#define N 16384
#define M 64
#define FULLM 0xFFFFFFFFu

// scratch (device globals — no allocation allowed)
__device__ float g_s[B * N];        // exp(beta*cos) from k1
__device__ float g_part[B * 256];   // per-block partial sums (k1 grid.x = 256)

// ---------------------------------------------------------------------------
// k1 (proven ~41.7us, unchanged from R14): exp(beta*cos) per row +
// deterministic per-block partial sum. 8 lanes/row, 2 rows/thread ->
// 4 LDG.128.CS in flight; ~55 regs. Block = 256 thr -> 64 rows. Grid (256,B).
// ---------------------------------------------------------------------------
__global__ __launch_bounds__(256) void k1_logits(
    const float* __restrict__ key,    // [B, M]
    const float* __restrict__ beta,   // [B, 1]
    const float* __restrict__ mem)    // [B, N, M]
{
    const int b    = blockIdx.y;
    const int tid  = threadIdx.x;
    const int l    = tid & 7;
    const int grp  = tid >> 3;
    const int row0 = blockIdx.x * 64;

    const float4* kp = reinterpret_cast<const float4*>(key + b * M);
    const float4 ka = kp[l];
    const float4 kb = kp[l + 8];
    float ks = ka.x * ka.x + ka.y * ka.y + ka.z * ka.z + ka.w * ka.w
             + kb.x * kb.x + kb.y * kb.y + kb.z * kb.z + kb.w * kb.w;

    float4 ma[2], mb[2];
#pragma unroll
    for (int u = 0; u < 2; ++u) {
        const int row = row0 + u * 32 + grp;
        const float4* mp = reinterpret_cast<const float4*>(
            mem + ((size_t)b * N + row) * M);
        ma[u] = __ldcs(mp + l);
        mb[u] = __ldcs(mp + l + 8);
    }

    float dt[2], ms[2];
#pragma unroll
    for (int u = 0; u < 2; ++u) {
        dt[u] = ka.x * ma[u].x + ka.y * ma[u].y + ka.z * ma[u].z + ka.w * ma[u].w
              + kb.x * mb[u].x + kb.y * mb[u].y + kb.z * mb[u].z + kb.w * mb[u].w;
        ms[u] = ma[u].x * ma[u].x + ma[u].y * ma[u].y + ma[u].z * ma[u].z + ma[u].w * ma[u].w
              + mb[u].x * mb[u].x + mb[u].y * mb[u].y + mb[u].z * mb[u].z + mb[u].w * mb[u].w;
    }

#pragma unroll
    for (int off = 1; off <= 4; off <<= 1) {
        ks    += __shfl_xor_sync(FULLM, ks,    off);
        dt[0] += __shfl_xor_sync(FULLM, dt[0], off);
        dt[1] += __shfl_xor_sync(FULLM, dt[1], off);
        ms[0] += __shfl_xor_sync(FULLM, ms[0], off);
        ms[1] += __shfl_xor_sync(FULLM, ms[1], off);
    }

    float esum = 0.0f;
    if (l == 0) {
        const float kn = sqrtf(ks);
        const float be = __ldg(beta + b);
#pragma unroll
        for (int u = 0; u < 2; ++u) {
            const int row = row0 + u * 32 + grp;
            const float denom = fmaxf(kn * sqrtf(ms[u]), 1e-8f);
            const float e = __expf(be * (dt[u] / denom));
            g_s[b * N + row] = e;
            esum += e;
        }
    }

    __shared__ float sred[8];
#pragma unroll
    for (int o = 16; o > 0; o >>= 1)
        esum += __shfl_xor_sync(FULLM, esum, o);
    if ((tid & 31) == 0) sred[tid >> 5] = esum;
    __syncthreads();
    if (tid == 0) {
        float s = 0.0f;
#pragma unroll
        for (int w = 0; w < 8; ++w) s += sred[w];
        g_part[b * 256 + blockIdx.x] = s;
    }
}

// ---------------------------------------------------------------------------
// k2 with PDL. Preamble (light): last vectors + raw l-edge publish (1 barrier).
// Post-sync: 4 vector g_s loads + raw e-edge publish + warp0-only S-reduce ->
// ONE barrier -> fused conv (ws = gS*conv(e) + og*conv(l), 6 FMA/elem) + pow
// -> psum reduce -> cluster combine (fixed rank order) -> store.
// Cluster-4, 256 CTAs x 256 thr.
// ---------------------------------------------------------------------------
__global__ __launch_bounds__(256) __cluster_dims__(4, 1, 1)
void k2_address(
    const float* __restrict__ gate,     // [B,1]
    const float* __restrict__ shift,    // [B,3]
    const float* __restrict__ sharpen,  // [B,1]
    const float* __restrict__ last,     // [B,N]
    float* __restrict__ out)            // [B,N]
{
    cg::cluster_group cluster = cg::this_cluster();

    const int cta  = blockIdx.x;     // 0..255
    const int b    = cta >> 2;
    const int q    = cta & 3;        // quarter of the batch (== cluster rank)
    const int tid  = threadIdx.x;
    const int warp = tid >> 5;       // 0..7
    const int lane = tid & 31;

    __shared__ float sred[8];
    __shared__ float sS;
    __shared__ float eLl[32], eRl[32];   // raw last edges  [warp*4+k]
    __shared__ float eLe[32], eRe[32];   // raw g_s  edges  [warp*4+k]
    __shared__ float sCLl, sCRl, sCLe, sCRe;
    __shared__ float cpsum;              // DSMEM target

    // ======= PDL preamble: last vectors + raw l edges =======
    const int base4 = (b << 12) + (q << 10);
    const float4* lp4 = reinterpret_cast<const float4*>(last);

    float4 a4[4];
#pragma unroll
    for (int k = 0; k < 4; ++k)
        a4[k] = lp4[base4 + k * 256 + tid];

    int edgeIdx = -1;
    if (tid == 0)   edgeIdx = b * N + (((q << 12) + N - 1) & (N - 1));
    if (tid == 255) edgeIdx = b * N + (((q << 12) + 4096) & (N - 1));

    const float g  = __ldg(gate + b);
    const float og = 1.0f - g;
    const float s0 = __ldg(shift + b * 3 + 0);
    const float s1 = __ldg(shift + b * 3 + 1);
    const float s2 = __ldg(shift + b * 3 + 2);
    const float sh = __ldg(sharpen + b);
    const float s0l = og * s0, s1l = og * s1, s2l = og * s2;

    if (lane == 0) {
#pragma unroll
        for (int k = 0; k < 4; ++k) eLl[warp * 4 + k] = a4[k].x;
    }
    if (lane == 31) {
#pragma unroll
        for (int k = 0; k < 4; ++k) eRl[warp * 4 + k] = a4[k].w;
    }
    if (tid == 0)   sCLl = last[edgeIdx];
    if (tid == 255) sCRl = last[edgeIdx];
    __syncthreads();  // l edges ready (pre-sync, overlapped with k1)

    // ======= wait for k1 grid completion (memory-visible) =======
    cudaGridDependencySynchronize();

    // post-sync loads (front-batched)
    const float4* sp4 = reinterpret_cast<const float4*>(g_s);
    float4 e4[4];
#pragma unroll
    for (int k = 0; k < 4; ++k)
        e4[k] = sp4[base4 + k * 256 + tid];

    float edgeS = 0.0f;
    if (edgeIdx >= 0) edgeS = g_s[edgeIdx];

    // publish raw e edges (no gS dependency)
    if (lane == 0) {
#pragma unroll
        for (int k = 0; k < 4; ++k) eLe[warp * 4 + k] = e4[k].x;
    }
    if (lane == 31) {
#pragma unroll
        for (int k = 0; k < 4; ++k) eRe[warp * 4 + k] = e4[k].w;
    }
    if (tid == 0)   sCLe = edgeS;
    if (tid == 255) sCRe = edgeS;

    // warp0-only softmax denominator
    if (warp == 0) {
        const float* pp = g_part + b * 256;
        float S = 0.0f;
#pragma unroll
        for (int j = 0; j < 8; ++j) S += pp[j * 32 + lane];
#pragma unroll
        for (int o = 16; o > 0; o >>= 1)
            S += __shfl_xor_sync(FULLM, S, o);
        if (lane == 0) sS = S;
    }
    __syncthreads();  // ONE barrier: sS + e edges both ready

    const float gS = g / sS;
    const float s0g = gS * s0, s1g = gS * s1, s2g = gS * s2;

    // fused conv: ws = gS*conv(e) + og*conv(l); p = ws^sh
    float4 p4[4];
    float psum = 0.0f;
#pragma unroll
    for (int k = 0; k < 4; ++k) {
        float le = __shfl_up_sync(FULLM, e4[k].w, 1);
        float ll = __shfl_up_sync(FULLM, a4[k].w, 1);
        if (lane == 0) {
            le = (warp > 0) ? eRe[(warp - 1) * 4 + k]
               : (k > 0)    ? eRe[7 * 4 + (k - 1)] : sCLe;
            ll = (warp > 0) ? eRl[(warp - 1) * 4 + k]
               : (k > 0)    ? eRl[7 * 4 + (k - 1)] : sCLl;
        }
        float re = __shfl_down_sync(FULLM, e4[k].x, 1);
        float rl = __shfl_down_sync(FULLM, a4[k].x, 1);
        if (lane == 31) {
            re = (warp < 7) ? eLe[(warp + 1) * 4 + k]
               : (k < 3)    ? eLe[k + 1] : sCRe;
            rl = (warp < 7) ? eLl[(warp + 1) * 4 + k]
               : (k < 3)    ? eLl[k + 1] : sCRl;
        }

        float4 ws;
        ws.x = fmaf(s0g, le,      fmaf(s0l, ll,      fmaf(s1g, e4[k].x,
               fmaf(s1l, a4[k].x, fmaf(s2g, e4[k].y, s2l * a4[k].y)))));
        ws.y = fmaf(s0g, e4[k].x, fmaf(s0l, a4[k].x, fmaf(s1g, e4[k].y,
               fmaf(s1l, a4[k].y, fmaf(s2g, e4[k].z, s2l * a4[k].z)))));
        ws.z = fmaf(s0g, e4[k].y, fmaf(s0l, a4[k].y, fmaf(s1g, e4[k].z,
               fmaf(s1l, a4[k].z, fmaf(s2g, e4[k].w, s2l * a4[k].w)))));
        ws.w = fmaf(s0g, e4[k].z, fmaf(s0l, a4[k].z, fmaf(s1g, e4[k].w,
               fmaf(s1l, a4[k].w, fmaf(s2g, re,      s2l * rl)))));

        p4[k].x = __powf(ws.x, sh);
        p4[k].y = __powf(ws.y, sh);
        p4[k].z = __powf(ws.z, sh);
        p4[k].w = __powf(ws.w, sh);
        psum += p4[k].x + p4[k].y + p4[k].z + p4[k].w;
    }

    // ---- CTA psum reduce (deterministic) ----
#pragma unroll
    for (int o = 16; o > 0; o >>= 1)
        psum += __shfl_xor_sync(FULLM, psum, o);
    if (lane == 0) sred[warp] = psum;
    __syncthreads();
    if (tid == 0) {
        float x = 0.0f;
#pragma unroll
        for (int w = 0; w < 8; ++w) x += sred[w];
        cpsum = x;
    }

    // ---- cluster combine via DSMEM (fixed rank order -> deterministic) ----
    cluster.sync();
    float P = 0.0f;
#pragma unroll
    for (int r = 0; r < 4; ++r)
        P += *cluster.map_shared_rank(&cpsum, r);
    cluster.sync();  // keep peer smem alive until everyone has read

    const float invP = 1.0f / (P + 1e-16f);

    float4* op4 = reinterpret_cast<float4*>(out);
#pragma unroll
    for (int k = 0; k < 4; ++k) {
        float4 p = p4[k];
        p.x *= invP; p.y *= invP; p.z *= invP; p.w *= invP;
        op4[base4 + k * 256 + tid] = p;
    }
}

extern "C" void kernel_launch(void* const* d_in, const int* in_sizes, int n_in,
                              void* d_out, int out_size) {
    const float* key     = (const float*)d_in[0];
    const float* beta    = (const float*)d_in[1];
    const float* gate    = (const float*)d_in[2];
    const float* shift   = (const float*)d_in[3];
    const float* sharpen = (const float*)d_in[4];
    const float* last    = (const float*)d_in[5];
    const float* mem     = (const float*)d_in[6];
    float* out = (float*)d_out;

    dim3 g1(N / 64, B);
    k1_logits<<<g1, 256>>>(key, beta, mem);

    cudaLaunchConfig_t cfg = {};
    cfg.gridDim  = dim3(B * 4);
    cfg.blockDim = dim3(256);
    cudaLaunchAttribute attrs[1];
    attrs[0].id = cudaLaunchAttributeProgrammaticStreamSerialization;
    attrs[0].val.programmaticStreamSerializationAllowed = 1;
    cfg.attrs = attrs;
    cfg.numAttrs = 1;
    cudaLaunchKernelEx(&cfg, k2_address, gate, shift, sharpen, last, out);
}